// round 7
// baseline (speedup 1.0000x reference)
#include <cuda_runtime.h>
#include <cstdint>

#define C_NUM 100000
#define D_NUM 256
#define B_NUM 1024
#define EPSV 1e-12f
#define GEMM_TILES_Y 782

__device__ float g_xnorm[B_NUM * D_NUM];   // tf32-rounded normalized x
__device__ float g_xexact[B_NUM * D_NUM];  // exact normalized x
__device__ float g_winv[C_NUM];
__device__ int   g_next[B_NUM];
__device__ int   g_head[B_NUM];

__device__ __forceinline__ uint32_t smem_u32(const void* p) {
    uint32_t a;
    asm("{ .reg .u64 t; cvta.to.shared.u64 t, %1; cvt.u32.u64 %0, t; }" : "=r"(a) : "l"(p));
    return a;
}
__device__ __forceinline__ unsigned f2tf(float f) {
    unsigned u;
    asm("cvt.rna.tf32.f32 %0, %1;" : "=r"(u) : "f"(f));
    return u;
}
__device__ __forceinline__ void cp16(uint32_t daddr, const void* gptr) {
    asm volatile("cp.async.cg.shared.global [%0], [%1], 16;" :: "r"(daddr), "l"(gptr) : "memory");
}
#define CP_COMMIT() asm volatile("cp.async.commit_group;" ::: "memory")

__device__ __forceinline__ void ldsm4(unsigned r[4], uint32_t addr) {
    asm volatile("ldmatrix.sync.aligned.m8n8.x4.shared.b16 {%0,%1,%2,%3}, [%4];"
                 : "=r"(r[0]), "=r"(r[1]), "=r"(r[2]), "=r"(r[3]) : "r"(addr));
}
__device__ __forceinline__ void mma_tf32(float d[4], const unsigned a[4], const unsigned b[2]) {
    asm volatile(
        "mma.sync.aligned.m16n8k8.row.col.f32.tf32.tf32.f32 "
        "{%0,%1,%2,%3}, {%4,%5,%6,%7}, {%8,%9}, {%0,%1,%2,%3};\n"
        : "+f"(d[0]), "+f"(d[1]), "+f"(d[2]), "+f"(d[3])
        : "r"(a[0]), "r"(a[1]), "r"(a[2]), "r"(a[3]),
          "r"(b[0]), "r"(b[1]));
}
__device__ __forceinline__ uint32_t sw128(uint32_t off) { return off ^ ((off >> 3) & 0x70); }

// ---------------------------------------------------------------------------
// K_PREP: fused  [blocks 0..1023]=xnorm  [1024]=chain  [1025..13524]=winv
// ---------------------------------------------------------------------------
__global__ void k_prep(const float* __restrict__ x, const int* __restrict__ tgt,
                       const float4* __restrict__ w4, float* __restrict__ out_t) {
    const int by = blockIdx.x;
    const int t = threadIdx.x;
    __shared__ float ws[8];
    __shared__ int st[B_NUM];

    if (by < B_NUM) {                    // ---- xnorm row `by` ----
        float v = x[by * D_NUM + t];
        float ss = v * v;
        #pragma unroll
        for (int o = 16; o; o >>= 1) ss += __shfl_xor_sync(0xffffffffu, ss, o);
        if ((t & 31) == 0) ws[t >> 5] = ss;
        __syncthreads();
        float tot = 0.f;
        #pragma unroll
        for (int i = 0; i < 8; ++i) tot += ws[i];
        float inv = 1.f / fmaxf(sqrtf(tot), EPSV);
        float xn = v * inv;
        g_xexact[by * D_NUM + t] = xn;
        g_xnorm[by * D_NUM + t] = __uint_as_float(f2tf(xn));
        if (t == 0) out_t[by] = (float)tgt[by];
    } else if (by == B_NUM) {            // ---- per-class occurrence chains ----
        #pragma unroll
        for (int k = 0; k < 4; ++k) {
            int i = t + k * 256;
            st[i] = tgt[i];
            g_next[i] = -1;
        }
        __syncthreads();
        #pragma unroll
        for (int k = 0; k < 4; ++k) {
            int i = t + k * 256;
            int me = st[i], prev = -1;
            for (int j = i - 1; j >= 0; --j)
                if (st[j] == me) { prev = j; break; }
            g_head[i] = (prev < 0) ? 1 : 0;
            if (prev >= 0) g_next[prev] = i;
        }
    } else {                             // ---- winv: one class per warp ----
        int gw = (by - B_NUM - 1) * 8 + (t >> 5);
        int lane = t & 31;
        if (gw < C_NUM) {
            const float4* row = w4 + (size_t)gw * 64;
            float4 a = row[lane];
            float4 b = row[lane + 32];
            float ss = a.x*a.x + a.y*a.y + a.z*a.z + a.w*a.w
                     + b.x*b.x + b.y*b.y + b.z*b.z + b.w*b.w;
            #pragma unroll
            for (int o = 16; o; o >>= 1) ss += __shfl_xor_sync(0xffffffffu, ss, o);
            if (lane == 0) g_winv[gw] = 1.f / fmaxf(sqrtf(ss), EPSV);
        }
    }
}

// ---------------------------------------------------------------------------
// K_GEMM: TF32 mma.sync. 256x128 CTA tile, 8 warps @ 64x64 (4x2), BK=32,
//         3-stage cp.async, single barrier/iter, per-CTA copy slice at tail.
// ---------------------------------------------------------------------------
#define BMT 256
#define BNT 128
#define NSTG 3
#define A_BYTES (BMT * 128)                 // 32768
#define STG_BYTES (A_BYTES + BNT * 128)     // 49152
#define OFF_TILE 1024
#define SMEM_BYTES (OFF_TILE + NSTG * STG_BYTES)   // 148480

__global__ __launch_bounds__(256, 1)
void k_gemm(const float* __restrict__ W, float* __restrict__ out,
            float4* __restrict__ nw4) {
    extern __shared__ char smem[];
    const uint32_t sb = smem_u32(smem);
    const int tid = threadIdx.x;
    const int lane = tid & 31, warp = tid >> 5;
    const int b0 = blockIdx.x * BMT;        // batch tile (x fastest => W L2 reuse)
    const int c0 = blockIdx.y * BNT;        // class tile
    const int wm = (warp & 3) * 64;
    const int wn = (warp >> 2) * 64;

    float* winv_s = (float*)smem;           // [128] = 30*winv
    if (tid < BNT) {
        int c = c0 + tid; if (c >= C_NUM) c = C_NUM - 1;
        winv_s[tid] = 30.0f * g_winv[c];
    }

    const char* Abase = (const char*)g_xnorm + (size_t)b0 * (D_NUM * 4);
    const char* Bbase = (const char*)W;

    auto issue_load = [&](int stage, int chunk) {
        uint32_t abuf = sb + OFF_TILE + stage * STG_BYTES;
        uint32_t bbuf = abuf + A_BYTES;
        #pragma unroll
        for (int i = 0; i < 12; ++i) {
            int slot = tid + i * 256;        // 0..3071
            if (slot < 2048) {               // A: 256 rows x 128B
                int r = slot >> 3, sg = (slot & 7) * 16;
                uint32_t so = sw128((uint32_t)(r * 128 + sg));
                cp16(abuf + so, Abase + (size_t)r * 1024 + chunk * 128 + sg);
            } else {                         // B: 128 rows x 128B
                int s2 = slot - 2048;
                int r = s2 >> 3, sg = (s2 & 7) * 16;
                uint32_t so = sw128((uint32_t)(r * 128 + sg));
                int row = c0 + r; if (row >= C_NUM) row = C_NUM - 1;
                cp16(bbuf + so, Bbase + (size_t)row * 1024 + chunk * 128 + sg);
            }
        }
        CP_COMMIT();
    };

    float acc[4][8][4];
    #pragma unroll
    for (int i = 0; i < 4; ++i)
        #pragma unroll
        for (int j = 0; j < 8; ++j)
            #pragma unroll
            for (int r = 0; r < 4; ++r) acc[i][j][r] = 0.f;

    uint32_t a_off[4], b_off[4];
    #pragma unroll
    for (int im = 0; im < 4; ++im)
        a_off[im] = (uint32_t)((wm + im * 16 + (lane & 15)) * 128 + ((lane >> 4) << 4));
    #pragma unroll
    for (int jp = 0; jp < 4; ++jp)
        b_off[jp] = (uint32_t)((wn + jp * 16 + ((lane >> 4) << 3) + (lane & 7)) * 128
                               + (((lane >> 3) & 1) << 4));

    issue_load(0, 0);
    issue_load(1, 1);

    #pragma unroll
    for (int c = 0; c < 8; ++c) {
        if (c < 7) asm volatile("cp.async.wait_group 1;" ::: "memory");
        else       asm volatile("cp.async.wait_group 0;" ::: "memory");
        __syncthreads();
        if (c + 2 < 8) issue_load((c + 2) % NSTG, c + 2);  // stage freed at this barrier

        const uint32_t abuf = sb + OFF_TILE + (c % NSTG) * STG_BYTES;
        const uint32_t bbuf = abuf + A_BYTES;
        #pragma unroll
        for (int ks = 0; ks < 4; ++ks) {
            unsigned af[4][4];
            #pragma unroll
            for (int im = 0; im < 4; ++im)
                ldsm4(af[im], abuf + sw128(a_off[im] + ks * 32));
            #pragma unroll
            for (int jph = 0; jph < 2; ++jph) {        // B in two halves: caps live regs
                unsigned bf[2][4];
                #pragma unroll
                for (int j2 = 0; j2 < 2; ++j2)
                    ldsm4(bf[j2], bbuf + sw128(b_off[jph * 2 + j2] + ks * 32));
                #pragma unroll
                for (int im = 0; im < 4; ++im) {
                    #pragma unroll
                    for (int j2 = 0; j2 < 2; ++j2) {
                        int jn = (jph * 2 + j2) * 2;
                        mma_tf32(acc[im][jn + 0], af[im], &bf[j2][0]);
                        mma_tf32(acc[im][jn + 1], af[im], &bf[j2][2]);
                    }
                }
            }
        }
    }
    __syncthreads();   // all reads of last stage done before tb reuse

    // epilogue: scale by 30*winv, smem transpose, coalesced float4 stores
    float* tb = (float*)(smem + OFF_TILE);   // [256][132] = 135KB, fits stage area
    const int g4 = lane >> 2, t4 = lane & 3;
    #pragma unroll
    for (int im = 0; im < 4; ++im) {
        int r = wm + im * 16 + g4;
        #pragma unroll
        for (int jn = 0; jn < 8; ++jn) {
            int col = wn + jn * 8 + t4 * 2;
            float s0 = winv_s[col], s1 = winv_s[col + 1];
            *(float2*)&tb[r * 132 + col] =
                make_float2(acc[im][jn][0] * s0, acc[im][jn][1] * s1);
            *(float2*)&tb[(r + 8) * 132 + col] =
                make_float2(acc[im][jn][2] * s0, acc[im][jn][3] * s1);
        }
    }
    __syncthreads();
    #pragma unroll
    for (int it = 0; it < 32; ++it) {
        int r = warp + it * 8;               // 0..255
        int colb = lane * 4;
        float4 val = *(const float4*)&tb[r * 132 + colb];
        int gc = c0 + colb;
        if (gc < C_NUM)
            *(float4*)&out[(size_t)(b0 + r) * C_NUM + gc] = val;
    }

    // ---- per-CTA copy slice: W -> new_weight (overlaps across waves) ----
    {
        const float4* src = (const float4*)W;
        const size_t n4 = (size_t)C_NUM * 64;
        size_t base = (size_t)(blockIdx.y * gridDim.x + blockIdx.x) * 2048 + tid;
        #pragma unroll
        for (int i = 0; i < 8; ++i) {
            size_t idx = base + (size_t)i * 256;
            if (idx < n4) nw4[idx] = src[idx];
        }
    }
}

// ---------------------------------------------------------------------------
// K_UPDATE: sequential momentum update per class chain (reads copied rows)
// ---------------------------------------------------------------------------
__global__ void k_update(const int* __restrict__ tgt, float* __restrict__ nw) {
    int b = blockIdx.x;
    if (!g_head[b]) return;
    int t = threadIdx.x;
    int y = tgt[b];
    float v = nw[(size_t)y * D_NUM + t];
    __shared__ float ws[8];
    int cur = b;
    while (cur >= 0) {
        v = 0.5f * v + 0.5f * g_xexact[cur * D_NUM + t];
        float ss = v * v;
        #pragma unroll
        for (int o = 16; o; o >>= 1) ss += __shfl_xor_sync(0xffffffffu, ss, o);
        __syncthreads();
        if ((t & 31) == 0) ws[t >> 5] = ss;
        __syncthreads();
        float tot = 0.f;
        #pragma unroll
        for (int i = 0; i < 8; ++i) tot += ws[i];
        v *= 1.f / fmaxf(sqrtf(tot), EPSV);
        cur = g_next[cur];
    }
    nw[(size_t)y * D_NUM + t] = v;
}

// ---------------------------------------------------------------------------
extern "C" void kernel_launch(void* const* d_in, const int* in_sizes, int n_in,
                              void* d_out, int out_size) {
    const float* x   = (const float*)d_in[0];
    const int*   tgt = (const int*)d_in[1];
    const float* w   = (const float*)d_in[2];
    float* out      = (float*)d_out;
    float* out_pred = out;                                  // [1024][100000]
    float* out_t    = out + (size_t)B_NUM * C_NUM;          // [1024]
    float* out_nw   = out_t + B_NUM;                        // [100000][256]

    static bool attr_set = false;
    if (!attr_set) {
        cudaFuncSetAttribute(k_gemm, cudaFuncAttributeMaxDynamicSharedMemorySize, SMEM_BYTES);
        attr_set = true;
    }

    k_prep<<<B_NUM + 1 + 12500, 256>>>(x, tgt, (const float4*)w, out_t);
    k_gemm<<<dim3(4, GEMM_TILES_Y), 256, SMEM_BYTES>>>(w, out_pred, (float4*)out_nw);
    k_update<<<B_NUM, 256>>>(tgt, out_nw);
}